// round 5
// baseline (speedup 1.0000x reference)
#include <cuda_runtime.h>

// FEDformer FourierBlock + out-projection + residual + series decomposition.
// R5 (= R4 re-bench after infra timeout, + x kept in registers across phases):
//  - fold Wq / per-node complex weights / Wo into one per-(node,mode) complex
//    32x32 matrix M (precompute kernel, __device__ scratch)
//  - direct-LDG 3-mode DFT with register twiddle rotation (warp-contig t)
//  - x values register-resident across forward/inverse phases
//  - register-resident sliding-window moving average with smem halo

#define NNODES 2000
#define LSEQ   96
#define DM     32
#define HH     4
#define EE     8
#define MM     3
#define KAVG   25
#define PAD    12
#define TPB    128

// per-(n,m) fused complex matrix, layout [n][m][d_in][d_out], float2 = (re,im)
static __device__ float2 g_A[(size_t)NNODES * MM * DM * DM];   // 49.15 MB

// ---------------------------------------------------------------------------
// Precompute: M[n][m][d_out][d_in] = (2/L) * sum_{h,o,e} Wo[d_out][h*8+o]
//                  * (W1 + i W2)[n][h][e][o][m] * Wq[h*8+e][d_in]
// stored transposed as g_A[n][m][d_in][d_out].
// ---------------------------------------------------------------------------
__global__ __launch_bounds__(TPB) void precomp_kernel(
    const float* __restrict__ Wq,
    const float* __restrict__ Wo,
    const float* __restrict__ W1,
    const float* __restrict__ W2)
{
    const int n = blockIdx.x;
    const int tid = threadIdx.x;
    const float scale = 2.0f / (float)LSEQ;

    __shared__ float sWq[DM*DM], sWo[DM*DM];
    __shared__ float s1[HH*EE*EE*MM], s2[HH*EE*EE*MM];
    __shared__ float B1[DM*33], B2[DM*33];          // [ho][d_in], pad 33

    {
        const float4* qg = (const float4*)Wq;
        const float4* og = (const float4*)Wo;
        float4* q4 = (float4*)sWq;  float4* o4 = (float4*)sWo;
        #pragma unroll
        for (int i = tid; i < (DM*DM)/4; i += TPB) { q4[i] = qg[i]; o4[i] = og[i]; }
        const float* w1g = W1 + (size_t)n * (HH*EE*EE*MM);
        const float* w2g = W2 + (size_t)n * (HH*EE*EE*MM);
        #pragma unroll
        for (int i = tid; i < HH*EE*EE*MM; i += TPB) { s1[i] = w1g[i]; s2[i] = w2g[i]; }
    }
    __syncthreads();

    for (int m = 0; m < MM; ++m) {
        // B[ho][d_in] = sum_e W{1,2}[h][e][o][m] * Wq[h*8+e][d_in]
        #pragma unroll
        for (int idx = tid; idx < DM*DM; idx += TPB) {
            const int ho = idx >> 5, din = idx & 31;
            const int h = ho >> 3, o = ho & 7;
            float a1 = 0.f, a2 = 0.f;
            #pragma unroll
            for (int e = 0; e < EE; ++e) {
                const float wq = sWq[(h*8 + e)*DM + din];
                const int wi = ((h*EE + e)*EE + o)*MM + m;
                a1 = fmaf(s1[wi], wq, a1);
                a2 = fmaf(s2[wi], wq, a2);
            }
            B1[ho*33 + din] = a1;
            B2[ho*33 + din] = a2;
        }
        __syncthreads();
        // M[d_out][d_in] = sum_ho Wo[d_out][ho] * B[ho][d_in]; write transposed
        #pragma unroll
        for (int idx = tid; idx < DM*DM; idx += TPB) {
            const int din = idx >> 5, dout = idx & 31;
            float mr = 0.f, mi = 0.f;
            #pragma unroll 8
            for (int k = 0; k < DM; ++k) {
                const int ho = (dout + k) & 31;          // conflict-free rotation
                const float wo = sWo[dout*DM + ho];
                mr = fmaf(wo, B1[ho*33 + din], mr);
                mi = fmaf(wo, B2[ho*33 + din], mi);
            }
            g_A[(((size_t)n*MM + m)*DM + din)*DM + dout] =
                make_float2(mr*scale, mi*scale);
        }
        __syncthreads();
    }
}

// ---------------------------------------------------------------------------
// Main fused kernel
// ---------------------------------------------------------------------------
__global__ __launch_bounds__(TPB, 6) void feldm_kernel(
    const float* __restrict__ x,
    const float* __restrict__ bo,
    float* __restrict__ out,
    int B)
{
    const int tid  = threadIdx.x;
    const int w    = tid >> 5;
    const int lane = tid & 31;
    const int n = blockIdx.x / B;        // n-major: batch siblings adjacent
    const int b = blockIdx.x - n * B;
    const size_t base = ((size_t)b * NNODES + n) * (size_t)(LSEQ * DM);

    __shared__ float spart[4*6*32];                 // DFT partials [w][6][d]
    __shared__ float sXfr[96], sXfi[96];
    __shared__ float sPr[96],  sPi[96];
    __shared__ float sxr[LSEQ * DM];                // xr for moving-avg halo

    // rotation step constants: e^{i*2pi*mode/96}, modes {1,4,5}
    float pc1, ps1, pc4, ps4, pc5, ps5;
    sincospif(1.0f/48.0f, &ps1, &pc1);
    sincospif(4.0f/48.0f, &ps4, &pc4);
    sincospif(5.0f/48.0f, &ps5, &pc5);
    // start angles at t0 = 24w are multiples of pi/2 (mode1,5: w*pi/2; mode4: 0)
    const float c0 = (w == 0) ? 1.f : (w == 2 ? -1.f : 0.f);
    const float s0 = (w == 1) ? 1.f : (w == 3 ? -1.f : 0.f);

    const int t0 = w * 24;
    const float* xg = x + base + (size_t)t0 * DM + lane;

    float r[24];                                    // x, later xr

    // ---- forward 3-mode DFT over own t-range, direct LDG, x kept in regs ----
    {
        float c1 = c0, s1 = s0, c4 = 1.f, s4 = 0.f, c5 = c0, s5 = s0;
        float ar1=0.f, ai1=0.f, ar2=0.f, ai2=0.f, ar3=0.f, ai3=0.f;
        #pragma unroll
        for (int i = 0; i < 24; ++i) {
            const float v = xg[i * DM];
            r[i] = v;
            ar1 = fmaf(v, c1, ar1);  ai1 = fmaf(v, s1, ai1);
            ar2 = fmaf(v, c4, ar2);  ai2 = fmaf(v, s4, ai2);
            ar3 = fmaf(v, c5, ar3);  ai3 = fmaf(v, s5, ai3);
            float nc, ns;
            nc = fmaf(c1, pc1, -s1*ps1); ns = fmaf(s1, pc1, c1*ps1); c1 = nc; s1 = ns;
            nc = fmaf(c4, pc4, -s4*ps4); ns = fmaf(s4, pc4, c4*ps4); c4 = nc; s4 = ns;
            nc = fmaf(c5, pc5, -s5*ps5); ns = fmaf(s5, pc5, c5*ps5); c5 = nc; s5 = ns;
        }
        spart[(w*6 + 0)*32 + lane] = ar1;  spart[(w*6 + 1)*32 + lane] = ai1;
        spart[(w*6 + 2)*32 + lane] = ar2;  spart[(w*6 + 3)*32 + lane] = ai2;
        spart[(w*6 + 4)*32 + lane] = ar3;  spart[(w*6 + 5)*32 + lane] = ai3;
    }
    __syncthreads();

    // ---- mid: reduce partials, P[m] = M[n,m] * Xf[m]  (warp m, m<3) ----
    if (w < 3) {
        const int m = w, j = lane;
        float fr = 0.f, fi = 0.f;
        #pragma unroll
        for (int ww = 0; ww < 4; ++ww) {
            fr += spart[(ww*6 + 2*m + 0)*32 + j];
            fi += spart[(ww*6 + 2*m + 1)*32 + j];
        }
        sXfr[m*32 + j] = fr;
        sXfi[m*32 + j] = -fi;            // Xf = sum x*(cos - i sin)
        __syncwarp();
        const float2* __restrict__ Am = g_A + ((size_t)n*MM + m) * (DM*DM);
        float pr = 0.f, pi = 0.f;
        #pragma unroll 8
        for (int d = 0; d < DM; ++d) {
            const float2 a = Am[d*DM + j];           // coalesced across lanes
            const float xr = sXfr[m*32 + d];         // broadcast
            const float xi = sXfi[m*32 + d];
            pr = fmaf(a.x, xr, fmaf(-a.y, xi, pr));
            pi = fmaf(a.x, xi, fmaf( a.y, xr, pi));
        }
        sPr[m*32 + j] = pr;
        sPi[m*32 + j] = pi;
    }
    __syncthreads();

    // ---- inverse 3-mode transform + residual into r[] (register xr) ----
    {
        const float Pr0 = sPr[     lane], Pi0 = sPi[     lane];
        const float Pr1 = sPr[32 + lane], Pi1 = sPi[32 + lane];
        const float Pr2 = sPr[64 + lane], Pi2 = sPi[64 + lane];
        const float bod = __ldg(bo + lane);
        float c1 = c0, s1 = s0, c4 = 1.f, s4 = 0.f, c5 = c0, s5 = s0;
        #pragma unroll
        for (int i = 0; i < 24; ++i) {
            float acc = bod;
            acc = fmaf(Pr0, c1, acc); acc = fmaf(-Pi0, s1, acc);
            acc = fmaf(Pr1, c4, acc); acc = fmaf(-Pi1, s4, acc);
            acc = fmaf(Pr2, c5, acc); acc = fmaf(-Pi2, s5, acc);
            r[i] += acc;
            sxr[(t0 + i)*DM + lane] = r[i];
            float nc, ns;
            nc = fmaf(c1, pc1, -s1*ps1); ns = fmaf(s1, pc1, c1*ps1); c1 = nc; s1 = ns;
            nc = fmaf(c4, pc4, -s4*ps4); ns = fmaf(s4, pc4, c4*ps4); c4 = nc; s4 = ns;
            nc = fmaf(c5, pc5, -s5*ps5); ns = fmaf(s5, pc5, c5*ps5); c5 = nc; s5 = ns;
        }
    }
    __syncthreads();

    // ---- sliding-window moving average; own range in regs, halo via smem ----
    {
        float win = 0.f;
        #pragma unroll
        for (int j = 0; j <= 12; ++j) win += r[j];
        if (w == 0) {
            win += 12.f * r[0];
        } else {
            #pragma unroll
            for (int j = 1; j <= 12; ++j) win += sxr[(t0 - j)*DM + lane];
        }
        float* og = out + base + (size_t)t0 * DM + lane;
        #pragma unroll
        for (int i = 0; i < 24; ++i) {
            og[i * DM] = r[i] - win * (1.0f/(float)KAVG);
            float vhi, vlo;
            if (i + 13 < 24)      vhi = r[i + 13];
            else if (w == 3)      vhi = r[23];
            else                  vhi = sxr[(t0 + i + 13)*DM + lane];
            if (i >= 12)          vlo = r[i - 12];
            else if (w == 0)      vlo = r[0];
            else                  vlo = sxr[(t0 + i - 12)*DM + lane];
            win += vhi - vlo;
        }
    }
}

extern "C" void kernel_launch(void* const* d_in, const int* in_sizes, int n_in,
                              void* d_out, int out_size) {
    // metadata order: x, Wq, bq, Wk, bk, Wv, bv, Wo, bo, W1, W2
    const float* x  = (const float*)d_in[0];
    const float* Wq = (const float*)d_in[1];
    const float* Wo = (const float*)d_in[7];
    const float* bo = (const float*)d_in[8];
    const float* W1 = (const float*)d_in[9];
    const float* W2 = (const float*)d_in[10];
    float* out = (float*)d_out;

    const int B = in_sizes[0] / (NNODES * LSEQ * DM);

    precomp_kernel<<<NNODES, TPB>>>(Wq, Wo, W1, W2);
    feldm_kernel<<<NNODES * B, TPB>>>(x, bo, out, B);
}

// round 6
// speedup vs baseline: 1.6071x; 1.6071x over previous
#include <cuda_runtime.h>

// FEDformer FourierBlock + out-projection + residual + series decomposition.
// R6 hybrid: R3's smem-staged mid GEMMs (low traffic) + R5's register-heavy
// outer phases (direct-LDG DFT, register twiddle rotation, register xr,
// halo-only smem moving average). Single kernel, no device scratch.

#define NNODES 2000
#define LSEQ   96
#define DM     32
#define HH     4
#define EE     8
#define MM     3
#define KAVG   25
#define PAD    12
#define TPB    128

__global__ __launch_bounds__(TPB, 6) void feldm_kernel(
    const float* __restrict__ x,
    const float* __restrict__ Wq,
    const float* __restrict__ Wo,
    const float* __restrict__ bo,
    const float* __restrict__ W1,
    const float* __restrict__ W2,
    float* __restrict__ out,
    int B)
{
    const int tid  = threadIdx.x;
    const int w    = tid >> 5;
    const int lane = tid & 31;
    const int n = blockIdx.x / B;        // n-major: batch siblings adjacent
    const int b = blockIdx.x - n * B;
    const size_t base = ((size_t)b * NNODES + n) * (size_t)(LSEQ * DM);

    __shared__ float sw1[HH*EE*EE*MM];              // 3 KB  per-node W1
    __shared__ float sw2[HH*EE*EE*MM];              // 3 KB  per-node W2
    __shared__ float sWq[DM*DM];                    // 4 KB
    __shared__ float sWo[DM*DM];                    // 4 KB
    __shared__ float spart[4*6*32];                 // 3 KB  DFT partials
    __shared__ float bAr[96], bAi[96];              // Xf, later Y
    __shared__ float bBr[96], bBi[96];              // X
    __shared__ float sPr[96], sPi[96];              // P
    __shared__ float sxr[LSEQ * DM];                // 12 KB xr (halo source)

    // ---- stage weights (coalesced) ----
    {
        const float4* qg = (const float4*)Wq;
        const float4* og = (const float4*)Wo;
        float4* q4 = (float4*)sWq;  float4* o4 = (float4*)sWo;
        #pragma unroll
        for (int i = tid; i < (DM*DM)/4; i += TPB) { q4[i] = qg[i]; o4[i] = og[i]; }
        const float* w1g = W1 + (size_t)n * (HH*EE*EE*MM);
        const float* w2g = W2 + (size_t)n * (HH*EE*EE*MM);
        #pragma unroll
        for (int i = tid; i < HH*EE*EE*MM; i += TPB) { sw1[i] = w1g[i]; sw2[i] = w2g[i]; }
    }

    // rotation step constants: e^{i*2pi*mode/96}, modes {1,4,5}
    float pc1, ps1, pc4, ps4, pc5, ps5;
    sincospif(1.0f/48.0f, &ps1, &pc1);
    sincospif(4.0f/48.0f, &ps4, &pc4);
    sincospif(5.0f/48.0f, &ps5, &pc5);
    // start angles at t0 = 24w are multiples of pi/2 (modes 1,5: w*pi/2; mode 4: 0)
    const float c0 = (w == 0) ? 1.f : (w == 2 ? -1.f : 0.f);
    const float s0 = (w == 1) ? 1.f : (w == 3 ? -1.f : 0.f);

    const int t0 = w * 24;
    const float* xg = x + base + (size_t)t0 * DM + lane;

    float r[24];                                    // x, later xr

    // ---- forward 3-mode DFT over own t-range, direct LDG, x kept in regs ----
    {
        float c1 = c0, s1 = s0, c4 = 1.f, s4 = 0.f, c5 = c0, s5 = s0;
        float ar1=0.f, ai1=0.f, ar2=0.f, ai2=0.f, ar3=0.f, ai3=0.f;
        #pragma unroll
        for (int i = 0; i < 24; ++i) {
            const float v = xg[i * DM];
            r[i] = v;
            ar1 = fmaf(v, c1, ar1);  ai1 = fmaf(v, s1, ai1);
            ar2 = fmaf(v, c4, ar2);  ai2 = fmaf(v, s4, ai2);
            ar3 = fmaf(v, c5, ar3);  ai3 = fmaf(v, s5, ai3);
            float nc, ns;
            nc = fmaf(c1, pc1, -s1*ps1); ns = fmaf(s1, pc1, c1*ps1); c1 = nc; s1 = ns;
            nc = fmaf(c4, pc4, -s4*ps4); ns = fmaf(s4, pc4, c4*ps4); c4 = nc; s4 = ns;
            nc = fmaf(c5, pc5, -s5*ps5); ns = fmaf(s5, pc5, c5*ps5); c5 = nc; s5 = ns;
        }
        spart[(w*6 + 0)*32 + lane] = ar1;  spart[(w*6 + 1)*32 + lane] = ai1;
        spart[(w*6 + 2)*32 + lane] = ar2;  spart[(w*6 + 3)*32 + lane] = ai2;
        spart[(w*6 + 4)*32 + lane] = ar3;  spart[(w*6 + 5)*32 + lane] = ai3;
    }
    __syncthreads();

    // ---- mid phases (warp m < 3): reduce -> Wq -> node weights -> Wo ----
    if (w < 3) {
        const int m = w, j = lane;
        // reduce partials; Xf = sum x*(cos - i sin)
        float fr = 0.f, fi = 0.f;
        #pragma unroll
        for (int ww = 0; ww < 4; ++ww) {
            fr += spart[(ww*6 + 2*m + 0)*32 + j];
            fi += spart[(ww*6 + 2*m + 1)*32 + j];
        }
        bAr[m*32 + j] = fr;
        bAi[m*32 + j] = -fi;
        __syncwarp();
        // X = Xf @ Wq^T (rotated, conflict-free)
        float arr = 0.f, aii = 0.f;
        #pragma unroll 8
        for (int k = 0; k < 32; ++k) {
            const int dd = (j + k) & 31;
            const float wv = sWq[j*DM + dd];
            arr = fmaf(bAr[(m<<5) + dd], wv, arr);
            aii = fmaf(bAi[(m<<5) + dd], wv, aii);
        }
        bBr[m*32 + j] = arr;
        bBi[m*32 + j] = aii;
        __syncwarp();
        // Y[m][h][o] = sum_e X[m][h*8+e] * (W1 + i W2)[h][e][o][m]  -> bufA
        const int h = j >> 3, o = j & 7;
        float yr = 0.f, yi = 0.f;
        #pragma unroll
        for (int e = 0; e < EE; ++e) {
            const int wi = ((h*EE + e)*EE + o)*MM + m;
            const float w1v = sw1[wi], w2v = sw2[wi];
            const float xr = bBr[(m<<5) + (h<<3) + e];
            const float xi = bBi[(m<<5) + (h<<3) + e];
            yr = fmaf(xr, w1v, fmaf(-xi, w2v, yr));
            yi = fmaf(xr, w2v, fmaf( xi, w1v, yi));
        }
        __syncwarp();
        bAr[m*32 + j] = yr;
        bAi[m*32 + j] = yi;
        __syncwarp();
        // P = (2/L) * Y @ Wo^T (rotated)
        float pr = 0.f, pi = 0.f;
        #pragma unroll 8
        for (int k = 0; k < 32; ++k) {
            const int jj = (j + k) & 31;
            const float wv = sWo[j*DM + jj];
            pr = fmaf(bAr[(m<<5) + jj], wv, pr);
            pi = fmaf(bAi[(m<<5) + jj], wv, pi);
        }
        sPr[m*32 + j] = pr * (2.0f/(float)LSEQ);
        sPi[m*32 + j] = pi * (2.0f/(float)LSEQ);
    }
    __syncthreads();

    // ---- inverse 3-mode transform + residual into r[] (register xr) ----
    {
        const float Pr0 = sPr[     lane], Pi0 = sPi[     lane];
        const float Pr1 = sPr[32 + lane], Pi1 = sPi[32 + lane];
        const float Pr2 = sPr[64 + lane], Pi2 = sPi[64 + lane];
        const float bod = __ldg(bo + lane);
        float c1 = c0, s1 = s0, c4 = 1.f, s4 = 0.f, c5 = c0, s5 = s0;
        #pragma unroll
        for (int i = 0; i < 24; ++i) {
            float acc = bod;
            acc = fmaf(Pr0, c1, acc); acc = fmaf(-Pi0, s1, acc);
            acc = fmaf(Pr1, c4, acc); acc = fmaf(-Pi1, s4, acc);
            acc = fmaf(Pr2, c5, acc); acc = fmaf(-Pi2, s5, acc);
            r[i] += acc;
            sxr[(t0 + i)*DM + lane] = r[i];
            float nc, ns;
            nc = fmaf(c1, pc1, -s1*ps1); ns = fmaf(s1, pc1, c1*ps1); c1 = nc; s1 = ns;
            nc = fmaf(c4, pc4, -s4*ps4); ns = fmaf(s4, pc4, c4*ps4); c4 = nc; s4 = ns;
            nc = fmaf(c5, pc5, -s5*ps5); ns = fmaf(s5, pc5, c5*ps5); c5 = nc; s5 = ns;
        }
    }
    __syncthreads();

    // ---- sliding-window moving average; own range in regs, halo via smem ----
    {
        float win = 0.f;
        #pragma unroll
        for (int j = 0; j <= 12; ++j) win += r[j];
        if (w == 0) {
            win += 12.f * r[0];
        } else {
            #pragma unroll
            for (int j = 1; j <= 12; ++j) win += sxr[(t0 - j)*DM + lane];
        }
        float* og = out + base + (size_t)t0 * DM + lane;
        #pragma unroll
        for (int i = 0; i < 24; ++i) {
            og[i * DM] = r[i] - win * (1.0f/(float)KAVG);
            float vhi, vlo;
            if (i + 13 < 24)      vhi = r[i + 13];
            else if (w == 3)      vhi = r[23];
            else                  vhi = sxr[(t0 + i + 13)*DM + lane];
            if (i >= 12)          vlo = r[i - 12];
            else if (w == 0)      vlo = r[0];
            else                  vlo = sxr[(t0 + i - 12)*DM + lane];
            win += vhi - vlo;
        }
    }
}

extern "C" void kernel_launch(void* const* d_in, const int* in_sizes, int n_in,
                              void* d_out, int out_size) {
    // metadata order: x, Wq, bq, Wk, bk, Wv, bv, Wo, bo, W1, W2
    const float* x  = (const float*)d_in[0];
    const float* Wq = (const float*)d_in[1];
    const float* Wo = (const float*)d_in[7];
    const float* bo = (const float*)d_in[8];
    const float* W1 = (const float*)d_in[9];
    const float* W2 = (const float*)d_in[10];
    float* out = (float*)d_out;

    const int B = in_sizes[0] / (NNODES * LSEQ * DM);
    feldm_kernel<<<NNODES * B, TPB>>>(x, Wq, Wo, bo, W1, W2, out, B);
}